// round 3
// baseline (speedup 1.0000x reference)
#include <cuda_runtime.h>
#include <math.h>

// Problem constants (fixed by the reference generator)
#define DD 300
#define NMAX 100000
#define EMAX 200000

// ---------------- scratch (device globals; no allocation allowed) ----------
__device__ float g_e   [(size_t)EMAX * DD];   // edge features  [E,D]
__device__ float g_tmp [(size_t)EMAX * DD];   // Te; also t1 (first N*D) + hh (next N*D)
__device__ float g_h   [(size_t)NMAX * DD];   // node state h   [N,D]
__device__ float g_buf [(size_t)NMAX * DD];   // h + agg accumulator / addmat scratch
__device__ float g_stats[2 * DD];             // BN sum / sumsq

// ---------------- small elementwise kernels --------------------------------
__global__ void zero_stats_k() {
    int t = threadIdx.x;
    if (t < 2 * DD) g_stats[t] = 0.f;
}

__global__ void copy_k(const float* __restrict__ src, float* __restrict__ dst, long n) {
    long i = (long)blockIdx.x * blockDim.x + threadIdx.x;
    long stride = (long)gridDim.x * blockDim.x;
    for (; i < n; i += stride) dst[i] = src[i];
}

// Te[e,d] = relu(ea[e,0]*w1[0,d] + ea[e,1]*w1[1,d] + ea[e,2]*w1[2,d] + b1[d])
__global__ void edge_pre_k(const float* __restrict__ ea, const float* __restrict__ w1,
                           const float* __restrict__ b1, float* __restrict__ out, int E) {
    long idx = (long)blockIdx.x * blockDim.x + threadIdx.x;
    long total = (long)E * DD;
    if (idx >= total) return;
    int e = (int)(idx / DD), d = (int)(idx % DD);
    float v = ea[e*3+0]*w1[d] + ea[e*3+1]*w1[DD+d] + ea[e*3+2]*w1[2*DD+d] + b1[d];
    out[idx] = fmaxf(v, 0.f);
}

// t[i,d] = relu(ch[i]*w1[0,d] + fc[i]*w1[1,d] + b1[d]);  base[i,d] = emb[z[i],d]
__global__ void node_pre_k(const int* __restrict__ z, const float* __restrict__ ch,
                           const float* __restrict__ fc, const float* __restrict__ w1,
                           const float* __restrict__ b1, const float* __restrict__ emb,
                           float* __restrict__ t, float* __restrict__ base, int N) {
    long idx = (long)blockIdx.x * blockDim.x + threadIdx.x;
    long total = (long)N * DD;
    if (idx >= total) return;
    int i = (int)(idx / DD), d = (int)(idx % DD);
    float v = ch[i]*w1[d] + fc[i]*w1[DD+d] + b1[d];
    t[idx]    = fmaxf(v, 0.f);
    base[idx] = emb[(long)z[i]*DD + d];
}

// buf[dst] += relu(h[src] + e)  (one warp per edge)
__global__ void scatter_k(const float* __restrict__ h, const float* __restrict__ e,
                          const int* __restrict__ src, const int* __restrict__ dst,
                          float* __restrict__ buf, int E) {
    int warp = (int)(((long)blockIdx.x * blockDim.x + threadIdx.x) >> 5);
    int lane = threadIdx.x & 31;
    if (warp >= E) return;
    int s = src[warp], t = dst[warp];
    const float* hr = h + (long)s * DD;
    const float* er = e + (long)warp * DD;
    float* br = buf + (long)t * DD;
    #pragma unroll 4
    for (int d = lane; d < DD; d += 32) {
        float v = hr[d] + er[d];
        if (v > 0.f) atomicAdd(&br[d], v);
    }
}

// per-column sum / sumsq (coalesced: thread d reads column d of consecutive rows)
__global__ void bn_stats_k(const float* __restrict__ hh, int N) {
    int d = threadIdx.x;
    if (d >= DD) return;
    float s = 0.f, q = 0.f;
    for (int r = blockIdx.x; r < N; r += gridDim.x) {
        float v = hh[(long)r * DD + d];
        s += v; q += v * v;
    }
    atomicAdd(&g_stats[d], s);
    atomicAdd(&g_stats[DD + d], q);
}

// h = relu((hh - mu) * rstd * gamma + beta); also mirror into buf for next layer
__global__ void bn_apply_k(const float* __restrict__ hh, const float* __restrict__ gamma,
                           const float* __restrict__ beta, float* __restrict__ h,
                           float* __restrict__ buf, int N) {
    long idx = (long)blockIdx.x * blockDim.x + threadIdx.x;
    long total = (long)N * DD;
    if (idx >= total) return;
    int d = (int)(idx % DD);
    float invN = 1.f / (float)N;
    float mu  = g_stats[d] * invN;
    float var = g_stats[DD + d] * invN - mu * mu;
    float rstd = rsqrtf(var + 1e-5f);
    float v = (hh[idx] - mu) * rstd * gamma[d] + beta[d];
    v = fmaxf(v, 0.f);
    h[idx] = v;
    buf[idx] = v;
}

// ---------------- tiled fp32 GEMM: C = act(A[MxK] @ W[KxN] + bias [+ addmat]) ----
// BM=BN=128, BK=8, 256 threads, 8x8 micro-tile.
__global__ void sgemm_k(const float* __restrict__ A, const float* __restrict__ W,
                        const float* __restrict__ bias, const float* __restrict__ addmat,
                        float* __restrict__ C, int M, int N, int K, int doRelu) {
    __shared__ float As[8][128];
    __shared__ float Bs[8][132];
    int tid = threadIdx.x;
    int tx = tid & 15, ty = tid >> 4;
    int m0 = blockIdx.y * 128, n0 = blockIdx.x * 128;

    float acc[8][8];
    #pragma unroll
    for (int i = 0; i < 8; i++)
        #pragma unroll
        for (int j = 0; j < 8; j++) acc[i][j] = 0.f;

    int arow = tid >> 1, acol = (tid & 1) * 4;   // A tile: 128 rows x 8 k
    int brow = tid >> 5, bcol = (tid & 31) * 4;  // B tile: 8 k x 128 cols

    for (int k0 = 0; k0 < K; k0 += 8) {
        #pragma unroll
        for (int j = 0; j < 4; j++) {
            int kk = k0 + acol + j;
            int mm = m0 + arow;
            As[acol + j][arow] = (mm < M && kk < K) ? A[(long)mm * K + kk] : 0.f;
        }
        #pragma unroll
        for (int j = 0; j < 4; j++) {
            int nn = n0 + bcol + j;
            int kk = k0 + brow;
            Bs[brow][bcol + j] = (kk < K && nn < N) ? W[(long)kk * N + nn] : 0.f;
        }
        __syncthreads();
        #pragma unroll
        for (int kk = 0; kk < 8; kk++) {
            float a[8], b[8];
            #pragma unroll
            for (int i = 0; i < 8; i++) a[i] = As[kk][ty * 8 + i];
            #pragma unroll
            for (int j = 0; j < 8; j++) b[j] = Bs[kk][tx * 8 + j];
            #pragma unroll
            for (int i = 0; i < 8; i++)
                #pragma unroll
                for (int j = 0; j < 8; j++)
                    acc[i][j] = fmaf(a[i], b[j], acc[i][j]);
        }
        __syncthreads();
    }

    #pragma unroll
    for (int i = 0; i < 8; i++) {
        int m = m0 + ty * 8 + i;
        if (m >= M) continue;
        #pragma unroll
        for (int j = 0; j < 8; j++) {
            int n = n0 + tx * 8 + j;
            if (n >= N) continue;
            float v = acc[i][j] + bias[n];
            if (addmat) v += addmat[(long)m * N + n];
            if (doRelu) v = fmaxf(v, 0.f);
            C[(long)m * N + n] = v;
        }
    }
}

static void launch_sgemm(const float* A, const float* W, const float* b,
                         const float* addmat, float* C, int M, int N, int K, int relu) {
    dim3 grid((N + 127) / 128, (M + 127) / 128);
    sgemm_k<<<grid, 256>>>(A, W, b, addmat, C, M, N, K, relu);
}

// ---------------- driver ----------------------------------------------------
extern "C" void kernel_launch(void* const* d_in, const int* in_sizes, int n_in,
                              void* d_out, int out_size) {
    const int*   z    = (const int*)  d_in[0];
    const float* chir = (const float*)d_in[1];
    const float* fchg = (const float*)d_in[2];
    const int*   ei   = (const int*)  d_in[3];
    const float* ea   = (const float*)d_in[4];
    const float* emb  = (const float*)d_in[5];
    const float* nw1  = (const float*)d_in[6];
    const float* nb1  = (const float*)d_in[7];
    const float* nw2  = (const float*)d_in[8];
    const float* nb2  = (const float*)d_in[9];
    const float* ew1  = (const float*)d_in[10];
    const float* eb1  = (const float*)d_in[11];
    const float* ew2  = (const float*)d_in[12];
    const float* eb2  = (const float*)d_in[13];
    const float* gw1  = (const float*)d_in[14];
    const float* gb1  = (const float*)d_in[15];
    const float* gw2  = (const float*)d_in[16];
    const float* gb2  = (const float*)d_in[17];
    const float* gam  = (const float*)d_in[18];
    const float* bet  = (const float*)d_in[19];
    const float* ahw  = (const float*)d_in[20];
    const float* ahb  = (const float*)d_in[21];
    const float* chw  = (const float*)d_in[22];
    const float* chb  = (const float*)d_in[23];

    const int N = in_sizes[0];
    const int E = in_sizes[3] / 2;
    const int* src = ei;
    const int* dst = ei + E;

    float *pe, *ptmp, *ph, *pbuf;
    cudaGetSymbolAddress((void**)&pe,   g_e);
    cudaGetSymbolAddress((void**)&ptmp, g_tmp);
    cudaGetSymbolAddress((void**)&ph,   g_h);
    cudaGetSymbolAddress((void**)&pbuf, g_buf);

    const long ND = (long)N * DD;
    const long ED = (long)E * DD;
    float* pt1 = ptmp;        // [N,D]
    float* phh = ptmp + ND;   // [N,D]

    // ---- edge encoder: e = relu(ea @ ew1 + eb1) @ ew2 + eb2 ----
    edge_pre_k<<<(unsigned)((ED + 255) / 256), 256>>>(ea, ew1, eb1, ptmp, E);
    launch_sgemm(ptmp, ew2, eb2, nullptr, pe, E, DD, DD, 0);

    // ---- node init: h = emb[z] + relu(na @ nw1 + nb1) @ nw2 + nb2 ----
    node_pre_k<<<(unsigned)((ND + 255) / 256), 256>>>(z, chir, fchg, nw1, nb1, emb, pt1, pbuf, N);
    launch_sgemm(pt1, nw2, nb2, pbuf, ph, N, DD, DD, 0);

    // buf = h (base for layer-0 aggregation)
    copy_k<<<2048, 256>>>(ph, pbuf, ND);

    // ---- 5 GINE layers ----
    for (int l = 0; l < 5; l++) {
        // buf += relu(h[src] + e) scattered to dst
        scatter_k<<<(E + 7) / 8, 256>>>(ph, pe, src, dst, pbuf, E);
        // t1 = relu(buf @ W1 + b1)
        launch_sgemm(pbuf, gw1 + (long)l * DD * DD, gb1 + l * DD, nullptr, pt1, N, DD, DD, 1);
        // hh = t1 @ W2 + b2
        launch_sgemm(pt1, gw2 + (long)l * DD * DD, gb2 + l * DD, nullptr, phh, N, DD, DD, 0);
        // batchnorm (training stats) + relu; mirror into buf for next layer
        zero_stats_k<<<1, 2 * DD>>>();
        bn_stats_k<<<1184, 320>>>(phh, N);
        bn_apply_k<<<(unsigned)((ND + 255) / 256), 256>>>(phh, gam + l * DD, bet + l * DD, ph, pbuf, N);
    }

    // ---- heads ----
    float* out = (float*)d_out;
    launch_sgemm(ph, ahw, ahb, nullptr, out, N, 87, DD, 0);
    launch_sgemm(ph, chw, chb, nullptr, out + (long)N * 87, N, 6, DD, 0);
}

// round 4
// speedup vs baseline: 1.0007x; 1.0007x over previous
#include <cuda_runtime.h>
#include <math.h>

// Problem constants (fixed by the reference generator)
#define DD 300
#define NMAX 100000
#define EMAX 200000

// ---------------- scratch (device globals; no allocation allowed) ----------
__device__ float g_e   [(size_t)EMAX * DD];   // edge features  [E,D]
__device__ float g_tmp [(size_t)EMAX * DD];   // Te; also t1 (first N*D) + hh (next N*D)
__device__ float g_h   [(size_t)NMAX * DD];   // node state h   [N,D]
__device__ float g_buf [(size_t)NMAX * DD];   // h + agg accumulator / addmat scratch
__device__ float g_stats[2 * DD];             // BN sum / sumsq

// ---------------- small elementwise kernels --------------------------------
__global__ void zero_stats_k() {
    int t = threadIdx.x;
    if (t < 2 * DD) g_stats[t] = 0.f;
}

__global__ void copy_k(const float* __restrict__ src, float* __restrict__ dst, long n) {
    long i = (long)blockIdx.x * blockDim.x + threadIdx.x;
    long stride = (long)gridDim.x * blockDim.x;
    for (; i < n; i += stride) dst[i] = src[i];
}

// Te[e,d] = relu(ea[e,0]*w1[0,d] + ea[e,1]*w1[1,d] + ea[e,2]*w1[2,d] + b1[d])
__global__ void edge_pre_k(const float* __restrict__ ea, const float* __restrict__ w1,
                           const float* __restrict__ b1, float* __restrict__ out, int E) {
    long idx = (long)blockIdx.x * blockDim.x + threadIdx.x;
    long total = (long)E * DD;
    if (idx >= total) return;
    int e = (int)(idx / DD), d = (int)(idx % DD);
    float v = ea[e*3+0]*w1[d] + ea[e*3+1]*w1[DD+d] + ea[e*3+2]*w1[2*DD+d] + b1[d];
    out[idx] = fmaxf(v, 0.f);
}

// t[i,d] = relu(ch[i]*w1[0,d] + fc[i]*w1[1,d] + b1[d]);  base[i,d] = emb[z[i],d]
__global__ void node_pre_k(const int* __restrict__ z, const float* __restrict__ ch,
                           const float* __restrict__ fc, const float* __restrict__ w1,
                           const float* __restrict__ b1, const float* __restrict__ emb,
                           float* __restrict__ t, float* __restrict__ base, int N) {
    long idx = (long)blockIdx.x * blockDim.x + threadIdx.x;
    long total = (long)N * DD;
    if (idx >= total) return;
    int i = (int)(idx / DD), d = (int)(idx % DD);
    float v = ch[i]*w1[d] + fc[i]*w1[DD+d] + b1[d];
    t[idx]    = fmaxf(v, 0.f);
    base[idx] = emb[(long)z[i]*DD + d];
}

// buf[dst] += relu(h[src] + e)  (one warp per edge)
__global__ void scatter_k(const float* __restrict__ h, const float* __restrict__ e,
                          const int* __restrict__ src, const int* __restrict__ dst,
                          float* __restrict__ buf, int E) {
    int warp = (int)(((long)blockIdx.x * blockDim.x + threadIdx.x) >> 5);
    int lane = threadIdx.x & 31;
    if (warp >= E) return;
    int s = src[warp], t = dst[warp];
    const float* hr = h + (long)s * DD;
    const float* er = e + (long)warp * DD;
    float* br = buf + (long)t * DD;
    #pragma unroll 4
    for (int d = lane; d < DD; d += 32) {
        float v = hr[d] + er[d];
        if (v > 0.f) atomicAdd(&br[d], v);
    }
}

// per-column sum / sumsq (coalesced: thread d reads column d of consecutive rows)
__global__ void bn_stats_k(const float* __restrict__ hh, int N) {
    int d = threadIdx.x;
    if (d >= DD) return;
    float s = 0.f, q = 0.f;
    for (int r = blockIdx.x; r < N; r += gridDim.x) {
        float v = hh[(long)r * DD + d];
        s += v; q += v * v;
    }
    atomicAdd(&g_stats[d], s);
    atomicAdd(&g_stats[DD + d], q);
}

// h = relu((hh - mu) * rstd * gamma + beta); also mirror into buf for next layer
__global__ void bn_apply_k(const float* __restrict__ hh, const float* __restrict__ gamma,
                           const float* __restrict__ beta, float* __restrict__ h,
                           float* __restrict__ buf, int N) {
    long idx = (long)blockIdx.x * blockDim.x + threadIdx.x;
    long total = (long)N * DD;
    if (idx >= total) return;
    int d = (int)(idx % DD);
    float invN = 1.f / (float)N;
    float mu  = g_stats[d] * invN;
    float var = g_stats[DD + d] * invN - mu * mu;
    float rstd = rsqrtf(var + 1e-5f);
    float v = (hh[idx] - mu) * rstd * gamma[d] + beta[d];
    v = fmaxf(v, 0.f);
    h[idx] = v;
    buf[idx] = v;
}

// ---------------- tiled fp32 GEMM: C = act(A[MxK] @ W[KxN] + bias [+ addmat]) ----
// BM=BN=128, BK=8, 256 threads, 8x8 micro-tile.
__global__ void sgemm_k(const float* __restrict__ A, const float* __restrict__ W,
                        const float* __restrict__ bias, const float* __restrict__ addmat,
                        float* __restrict__ C, int M, int N, int K, int doRelu) {
    __shared__ float As[8][128];
    __shared__ float Bs[8][132];
    int tid = threadIdx.x;
    int tx = tid & 15, ty = tid >> 4;
    int m0 = blockIdx.y * 128, n0 = blockIdx.x * 128;

    float acc[8][8];
    #pragma unroll
    for (int i = 0; i < 8; i++)
        #pragma unroll
        for (int j = 0; j < 8; j++) acc[i][j] = 0.f;

    int arow = tid >> 1, acol = (tid & 1) * 4;   // A tile: 128 rows x 8 k
    int brow = tid >> 5, bcol = (tid & 31) * 4;  // B tile: 8 k x 128 cols

    for (int k0 = 0; k0 < K; k0 += 8) {
        #pragma unroll
        for (int j = 0; j < 4; j++) {
            int kk = k0 + acol + j;
            int mm = m0 + arow;
            As[acol + j][arow] = (mm < M && kk < K) ? A[(long)mm * K + kk] : 0.f;
        }
        #pragma unroll
        for (int j = 0; j < 4; j++) {
            int nn = n0 + bcol + j;
            int kk = k0 + brow;
            Bs[brow][bcol + j] = (kk < K && nn < N) ? W[(long)kk * N + nn] : 0.f;
        }
        __syncthreads();
        #pragma unroll
        for (int kk = 0; kk < 8; kk++) {
            float a[8], b[8];
            #pragma unroll
            for (int i = 0; i < 8; i++) a[i] = As[kk][ty * 8 + i];
            #pragma unroll
            for (int j = 0; j < 8; j++) b[j] = Bs[kk][tx * 8 + j];
            #pragma unroll
            for (int i = 0; i < 8; i++)
                #pragma unroll
                for (int j = 0; j < 8; j++)
                    acc[i][j] = fmaf(a[i], b[j], acc[i][j]);
        }
        __syncthreads();
    }

    #pragma unroll
    for (int i = 0; i < 8; i++) {
        int m = m0 + ty * 8 + i;
        if (m >= M) continue;
        #pragma unroll
        for (int j = 0; j < 8; j++) {
            int n = n0 + tx * 8 + j;
            if (n >= N) continue;
            float v = acc[i][j] + bias[n];
            if (addmat) v += addmat[(long)m * N + n];
            if (doRelu) v = fmaxf(v, 0.f);
            C[(long)m * N + n] = v;
        }
    }
}

static void launch_sgemm(const float* A, const float* W, const float* b,
                         const float* addmat, float* C, int M, int N, int K, int relu) {
    dim3 grid((N + 127) / 128, (M + 127) / 128);
    sgemm_k<<<grid, 256>>>(A, W, b, addmat, C, M, N, K, relu);
}

// ---------------- driver ----------------------------------------------------
extern "C" void kernel_launch(void* const* d_in, const int* in_sizes, int n_in,
                              void* d_out, int out_size) {
    const int*   z    = (const int*)  d_in[0];
    const float* chir = (const float*)d_in[1];
    const float* fchg = (const float*)d_in[2];
    const int*   ei   = (const int*)  d_in[3];
    const float* ea   = (const float*)d_in[4];
    const float* emb  = (const float*)d_in[5];
    const float* nw1  = (const float*)d_in[6];
    const float* nb1  = (const float*)d_in[7];
    const float* nw2  = (const float*)d_in[8];
    const float* nb2  = (const float*)d_in[9];
    const float* ew1  = (const float*)d_in[10];
    const float* eb1  = (const float*)d_in[11];
    const float* ew2  = (const float*)d_in[12];
    const float* eb2  = (const float*)d_in[13];
    const float* gw1  = (const float*)d_in[14];
    const float* gb1  = (const float*)d_in[15];
    const float* gw2  = (const float*)d_in[16];
    const float* gb2  = (const float*)d_in[17];
    const float* gam  = (const float*)d_in[18];
    const float* bet  = (const float*)d_in[19];
    const float* ahw  = (const float*)d_in[20];
    const float* ahb  = (const float*)d_in[21];
    const float* chw  = (const float*)d_in[22];
    const float* chb  = (const float*)d_in[23];

    const int N = in_sizes[0];
    const int E = in_sizes[3] / 2;
    const int* src = ei;
    const int* dst = ei + E;

    float *pe, *ptmp, *ph, *pbuf;
    cudaGetSymbolAddress((void**)&pe,   g_e);
    cudaGetSymbolAddress((void**)&ptmp, g_tmp);
    cudaGetSymbolAddress((void**)&ph,   g_h);
    cudaGetSymbolAddress((void**)&pbuf, g_buf);

    const long ND = (long)N * DD;
    const long ED = (long)E * DD;
    float* pt1 = ptmp;        // [N,D]
    float* phh = ptmp + ND;   // [N,D]

    // ---- edge encoder: e = relu(ea @ ew1 + eb1) @ ew2 + eb2 ----
    edge_pre_k<<<(unsigned)((ED + 255) / 256), 256>>>(ea, ew1, eb1, ptmp, E);
    launch_sgemm(ptmp, ew2, eb2, nullptr, pe, E, DD, DD, 0);

    // ---- node init: h = emb[z] + relu(na @ nw1 + nb1) @ nw2 + nb2 ----
    node_pre_k<<<(unsigned)((ND + 255) / 256), 256>>>(z, chir, fchg, nw1, nb1, emb, pt1, pbuf, N);
    launch_sgemm(pt1, nw2, nb2, pbuf, ph, N, DD, DD, 0);

    // buf = h (base for layer-0 aggregation)
    copy_k<<<2048, 256>>>(ph, pbuf, ND);

    // ---- 5 GINE layers ----
    for (int l = 0; l < 5; l++) {
        // buf += relu(h[src] + e) scattered to dst
        scatter_k<<<(E + 7) / 8, 256>>>(ph, pe, src, dst, pbuf, E);
        // t1 = relu(buf @ W1 + b1)
        launch_sgemm(pbuf, gw1 + (long)l * DD * DD, gb1 + l * DD, nullptr, pt1, N, DD, DD, 1);
        // hh = t1 @ W2 + b2
        launch_sgemm(pt1, gw2 + (long)l * DD * DD, gb2 + l * DD, nullptr, phh, N, DD, DD, 0);
        // batchnorm (training stats) + relu; mirror into buf for next layer
        zero_stats_k<<<1, 2 * DD>>>();
        bn_stats_k<<<1184, 320>>>(phh, N);
        bn_apply_k<<<(unsigned)((ND + 255) / 256), 256>>>(phh, gam + l * DD, bet + l * DD, ph, pbuf, N);
    }

    // ---- heads ----
    float* out = (float*)d_out;
    launch_sgemm(ph, ahw, ahb, nullptr, out, N, 87, DD, 0);
    launch_sgemm(ph, chw, chb, nullptr, out + (long)N * 87, N, 6, DD, 0);
}